// round 6
// baseline (speedup 1.0000x reference)
#include <cuda_runtime.h>
#include <cuda_bf16.h>
#include <math.h>
#include <stdint.h>

#define B_  4
#define S_  4096
#define D_  1024
#define H_  16
#define R_  256
#define DK_ 64
#define M_  (B_*S_)

// ---------------- scratch (device globals; no allocation allowed) ----------------
__device__ __nv_bfloat16 g_ah[M_*D_];           // gemm activation hi/lo staging
__device__ __nv_bfloat16 g_al[M_*D_];
__device__ __nv_bfloat16 g_wh[D_*D_];           // gemm weight hi/lo staging
__device__ __nv_bfloat16 g_wl[D_*D_];

__device__ __nv_bfloat16 g_qh[M_*D_], g_ql[M_*D_];   // q/k/v split (gemm epilogues)
__device__ __nv_bfloat16 g_kh[M_*D_], g_kl[M_*D_];
__device__ __nv_bfloat16 g_vh[M_*D_], g_vl[M_*D_];

__device__ __nv_bfloat16 g_eh[H_*S_*R_], g_el[H_*S_*R_];   // E/F split
__device__ __nv_bfloat16 g_fh[H_*S_*R_], g_fl[H_*S_*R_];

#define KPN (B_*H_*DK_*R_)
__device__ __nv_bfloat16 g_kph[KPN], g_kpl[KPN];     // kp/vp split (proj epilogue)
__device__ __nv_bfloat16 g_vph[KPN], g_vpl[KPN];

// ============================================================================
// helpers (baseline PTX only — plain sm_100 target)
// ============================================================================
__device__ __forceinline__ uint32_t smem_u32(const void* p) {
    uint32_t a;
    asm("{ .reg .u64 t; cvta.to.shared.u64 t, %1; cvt.u32.u64 %0, t; }" : "=r"(a) : "l"(p));
    return a;
}
__device__ __forceinline__ void cp16(uint32_t dst, const void* src) {
    asm volatile("cp.async.cg.shared.global [%0], [%1], 16;" :: "r"(dst), "l"(src) : "memory");
}
__device__ __forceinline__ void cp_commit() {
    asm volatile("cp.async.commit_group;" ::: "memory");
}
template<int N> __device__ __forceinline__ void cp_wait() {
    asm volatile("cp.async.wait_group %0;" :: "n"(N) : "memory");
}
#define LDSM4(r, addr)                                                            \
    asm volatile("ldmatrix.sync.aligned.m8n8.x4.shared.b16 {%0,%1,%2,%3}, [%4];"  \
        : "=r"((r)[0]), "=r"((r)[1]), "=r"((r)[2]), "=r"((r)[3]) : "r"(addr))
#define LDSM4T(r, addr)                                                                 \
    asm volatile("ldmatrix.sync.aligned.m8n8.x4.trans.shared.b16 {%0,%1,%2,%3}, [%4];"  \
        : "=r"((r)[0]), "=r"((r)[1]), "=r"((r)[2]), "=r"((r)[3]) : "r"(addr))
#define MMA16816(d, a, b0, b1)                                                    \
    asm volatile("mma.sync.aligned.m16n8k16.row.col.f32.bf16.bf16.f32 "           \
        "{%0,%1,%2,%3}, {%4,%5,%6,%7}, {%8,%9}, {%0,%1,%2,%3};"                   \
        : "+f"((d)[0]), "+f"((d)[1]), "+f"((d)[2]), "+f"((d)[3])                  \
        : "r"((a)[0]), "r"((a)[1]), "r"((a)[2]), "r"((a)[3]), "r"(b0), "r"(b1))

__device__ __forceinline__ uint32_t pack_bf2(float a, float b) {
    __nv_bfloat162 t = __floats2bfloat162_rn(a, b);
    return *(uint32_t*)&t;
}

// ============================================================================
// fp32 -> (hi, lo) bf16 split conversion.
// sel 0: src -> g_ah/g_al ; 1: W -> g_wh/g_wl ; 2: E -> g_eh/g_el ; 3: F -> g_fh/g_fl
// ============================================================================
__global__ __launch_bounds__(256) void conv_kernel(const float* __restrict__ src,
                                                   int sel, int n4)
{
    __nv_bfloat16 *hi, *lo;
    if (sel == 0)      { hi = g_ah; lo = g_al; }
    else if (sel == 1) { hi = g_wh; lo = g_wl; }
    else if (sel == 2) { hi = g_eh; lo = g_el; }
    else               { hi = g_fh; lo = g_fl; }
    int i = blockIdx.x * blockDim.x + threadIdx.x;
    if (i >= n4) return;
    float4 v = ((const float4*)src)[i];
    __nv_bfloat16 h[4], l[4];
    h[0] = __float2bfloat16(v.x); l[0] = __float2bfloat16(v.x - __bfloat162float(h[0]));
    h[1] = __float2bfloat16(v.y); l[1] = __float2bfloat16(v.y - __bfloat162float(h[1]));
    h[2] = __float2bfloat16(v.z); l[2] = __float2bfloat16(v.z - __bfloat162float(h[2]));
    h[3] = __float2bfloat16(v.w); l[3] = __float2bfloat16(v.w - __bfloat162float(h[3]));
    *(uint2*)(hi + 4 * (size_t)i) = *(uint2*)h;
    *(uint2*)(lo + 4 * (size_t)i) = *(uint2*)l;
}

// ============================================================================
// Split-bf16 HMMA GEMM: C = A @ W^T + bias. 128x128x32 CTA, 3-pass split.
// 512 threads, 4x4 warp grid, 32x32 warp tile, 3-stage cp.async pipeline.
// csel 0/1/2 -> write split bf16 (qh/ql, kh/kl, vh/vl); csel 3 -> fp32 Cext.
// ============================================================================
#define TILE_B   10240          // 128 rows * 80 bytes
#define STAGE_B  (4*TILE_B)     // AH, AL, BH, BL
#define GSMEM_B  (3*STAGE_B)    // 122880 (3 stages)
#define NIT      (D_/32)        // 32 k-iterations

__device__ __forceinline__ void mm_issue(uint32_t sbase, int buf, int it,
                                         int m0, int n0, int tid)
{
    const int k0 = it * 32;
    const uint32_t sb = sbase + buf * STAGE_B;
    const int row = tid >> 2;            // 0..127
    const int c16 = tid & 3;             // 16B chunk within 64B row
    const uint32_t dst = sb + row * 80 + c16 * 16;
    const size_t ga = (size_t)(m0 + row) * D_ + k0 + c16 * 8;
    const size_t gb = (size_t)(n0 + row) * D_ + k0 + c16 * 8;
    cp16(dst,              g_ah + ga);
    cp16(dst + TILE_B,     g_al + ga);
    cp16(dst + 2*TILE_B,   g_wh + gb);
    cp16(dst + 3*TILE_B,   g_wl + gb);
    cp_commit();
}

__global__ __launch_bounds__(512, 1) void mm_gemm(const float* __restrict__ bias,
                                                  float* Cext, int csel)
{
    extern __shared__ char smem[];
    const uint32_t sbase = smem_u32(smem);
    const int tid  = threadIdx.x;
    const int wid  = tid >> 5;
    const int lane = tid & 31;
    const int wm   = wid & 3;       // 4 warps along M (32 rows each)
    const int wn   = wid >> 2;      // 4 warps along N (32 cols each)
    const int m0   = blockIdx.y * 128;
    const int n0   = blockIdx.x * 128;

    float acc[2][4][4];
    #pragma unroll
    for (int mt = 0; mt < 2; mt++)
        #pragma unroll
        for (int nt = 0; nt < 4; nt++)
            #pragma unroll
            for (int e = 0; e < 4; e++) acc[mt][nt][e] = 0.f;

    const uint32_t lrow  = lane & 15;
    const uint32_t lhalf = (lane >> 4) * 16;

    mm_issue(sbase, 0, 0, m0, n0, tid);
    mm_issue(sbase, 1, 1, m0, n0, tid);

    for (int it = 0; it < NIT; it++) {
        if (it + 2 < NIT)       { mm_issue(sbase, (it + 2) % 3, it + 2, m0, n0, tid); cp_wait<2>(); }
        else if (it + 2 == NIT) { cp_wait<1>(); }
        else                    { cp_wait<0>(); }
        __syncthreads();

        const uint32_t sb = sbase + (it % 3) * STAGE_B;
        #pragma unroll
        for (int ks = 0; ks < 2; ks++) {
            const uint32_t koff = ks * 32;
            uint32_t bh[2][4], bl[2][4];
            #pragma unroll
            for (int ng = 0; ng < 2; ng++) {
                const uint32_t addr = sb + 2 * TILE_B
                    + (wn * 32 + ng * 16 + lrow) * 80 + koff + lhalf;
                LDSM4(bh[ng], addr);
                LDSM4(bl[ng], addr + TILE_B);
            }
            uint32_t a[2][4];
            #pragma unroll
            for (int mt = 0; mt < 2; mt++) {
                const uint32_t addr = sb
                    + (wm * 32 + mt * 16 + lrow) * 80 + koff + lhalf;
                LDSM4(a[mt], addr);
            }
            #pragma unroll
            for (int mt = 0; mt < 2; mt++)
                #pragma unroll
                for (int nt = 0; nt < 4; nt++) {
                    const int ng = nt >> 1, hf = nt & 1;
                    MMA16816(acc[mt][nt], a[mt], bh[ng][hf], bh[ng][hf + 2]);
                    MMA16816(acc[mt][nt], a[mt], bl[ng][hf], bl[ng][hf + 2]);
                }
            #pragma unroll
            for (int mt = 0; mt < 2; mt++) {
                const uint32_t addr = sb + TILE_B
                    + (wm * 32 + mt * 16 + lrow) * 80 + koff + lhalf;
                LDSM4(a[mt], addr);
            }
            #pragma unroll
            for (int mt = 0; mt < 2; mt++)
                #pragma unroll
                for (int nt = 0; nt < 4; nt++) {
                    const int ng = nt >> 1, hf = nt & 1;
                    MMA16816(acc[mt][nt], a[mt], bh[ng][hf], bh[ng][hf + 2]);
                }
        }
        __syncthreads();
    }

    const int grp = lane >> 2;
    const int qp  = lane & 3;
    if (csel < 3) {
        __nv_bfloat16 *OH, *OL;
        if (csel == 0)      { OH = g_qh; OL = g_ql; }
        else if (csel == 1) { OH = g_kh; OL = g_kl; }
        else                { OH = g_vh; OL = g_vl; }
        #pragma unroll
        for (int mt = 0; mt < 2; mt++) {
            const int r0 = m0 + wm * 32 + mt * 16 + grp;
            #pragma unroll
            for (int nt = 0; nt < 4; nt++) {
                const int col = n0 + wn * 32 + nt * 8 + qp * 2;
                const float b0 = bias[col], b1 = bias[col + 1];
                float v0 = acc[mt][nt][0] + b0, v1 = acc[mt][nt][1] + b1;
                float v2 = acc[mt][nt][2] + b0, v3 = acc[mt][nt][3] + b1;
                float h0 = __bfloat162float(__float2bfloat16(v0));
                float h1 = __bfloat162float(__float2bfloat16(v1));
                float h2 = __bfloat162float(__float2bfloat16(v2));
                float h3 = __bfloat162float(__float2bfloat16(v3));
                *(uint32_t*)(OH + (size_t)r0 * D_ + col)       = pack_bf2(v0, v1);
                *(uint32_t*)(OL + (size_t)r0 * D_ + col)       = pack_bf2(v0 - h0, v1 - h1);
                *(uint32_t*)(OH + (size_t)(r0 + 8) * D_ + col) = pack_bf2(v2, v3);
                *(uint32_t*)(OL + (size_t)(r0 + 8) * D_ + col) = pack_bf2(v2 - h2, v3 - h3);
            }
        }
    } else {
        #pragma unroll
        for (int mt = 0; mt < 2; mt++) {
            const int r0 = m0 + wm * 32 + mt * 16 + grp;
            #pragma unroll
            for (int nt = 0; nt < 4; nt++) {
                const int col = n0 + wn * 32 + nt * 8 + qp * 2;
                const float b0 = bias[col], b1 = bias[col + 1];
                *(float2*)(Cext + (size_t)r0 * D_ + col) =
                    make_float2(acc[mt][nt][0] + b0, acc[mt][nt][1] + b1);
                *(float2*)(Cext + (size_t)(r0 + 8) * D_ + col) =
                    make_float2(acc[mt][nt][2] + b0, acc[mt][nt][3] + b1);
            }
        }
    }
}

// ============================================================================
// proj (HMMA): kp[bh][d][r] = sum_s k[b][s][hd] * E[h][s][r]  (split 3-pass)
// One CTA per (which,bh): grid.x = 128.  C = 64(d) x 256(r), K = S = 4096.
// ============================================================================
#define PJ_KH 0
#define PJ_KL 4608
#define PJ_EH 9216
#define PJ_EL 26112
#define PJ_STAGE 43008
#define PJ_SMEM  (2*PJ_STAGE)

__global__ __launch_bounds__(256, 1) void proj_mma()
{
    extern __shared__ char sm[];
    const uint32_t sb = smem_u32(sm);
    const int bx = blockIdx.x;
    const int which = bx >> 6, bh = bx & 63;
    const int b = bh >> 4, h = bh & 15;
    const __nv_bfloat16* Ah = which ? g_vh : g_kh;
    const __nv_bfloat16* Al = which ? g_vl : g_kl;
    const __nv_bfloat16* Eh = which ? g_fh : g_eh;
    const __nv_bfloat16* El = which ? g_fl : g_el;
    __nv_bfloat16* Oh = which ? g_vph : g_kph;
    __nv_bfloat16* Ol = which ? g_vpl : g_kpl;

    const int tid = threadIdx.x, wid = tid >> 5, lane = tid & 31;
    const int wn = wid;

    float acc[4][4][4];
    #pragma unroll
    for (int mt = 0; mt < 4; mt++)
        #pragma unroll
        for (int nt = 0; nt < 4; nt++)
            #pragma unroll
            for (int e = 0; e < 4; e++) acc[mt][nt][e] = 0.f;

    auto issue = [&](int buf, int it) {
        const int s0 = it * 32;
        const uint32_t st = sb + buf * PJ_STAGE;
        #pragma unroll
        for (int i = 0; i < 10; i++) {
            const int c = tid + i * 256;
            uint32_t dst; const __nv_bfloat16* src;
            if (c < 512) {
                const int sp = c >> 8, idx = c & 255, row = idx >> 3, ch = idx & 7;
                dst = st + (sp ? PJ_KL : PJ_KH) + row * 144 + ch * 16;
                src = (sp ? Al : Ah) + ((size_t)(b * S_ + s0 + row) * D_ + h * DK_ + ch * 8);
            } else {
                const int i2 = c - 512, sp = i2 >> 10, idx = i2 & 1023;
                const int row = idx >> 5, ch = idx & 31;
                dst = st + (sp ? PJ_EL : PJ_EH) + row * 528 + ch * 16;
                src = (sp ? El : Eh) + ((size_t)(h * S_ + s0 + row) * R_ + ch * 8);
            }
            cp16(dst, src);
        }
        cp_commit();
    };

    issue(0, 0);
    const uint32_t arow = (lane & 7) + ((lane >> 4) << 3);
    const uint32_t acol = ((lane >> 3) & 1) * 16;
    const uint32_t brow = lane & 15;
    const uint32_t bcol = (lane >> 4) * 16;

    for (int it = 0; it < 128; it++) {
        if (it + 1 < 128) { issue((it + 1) & 1, it + 1); cp_wait<1>(); }
        else              { cp_wait<0>(); }
        __syncthreads();
        const uint32_t st = sb + (it & 1) * PJ_STAGE;
        #pragma unroll
        for (int ks = 0; ks < 2; ks++) {
            uint32_t ah[4][4], al[4][4];
            #pragma unroll
            for (int mt = 0; mt < 4; mt++) {
                const uint32_t addr = st + PJ_KH
                    + (ks * 16 + arow) * 144 + mt * 32 + acol;
                LDSM4T(ah[mt], addr);
                LDSM4T(al[mt], addr + (PJ_KL - PJ_KH));
            }
            #pragma unroll
            for (int bb = 0; bb < 2; bb++) {
                uint32_t bhh[4], bll[4];
                const uint32_t addr = st + PJ_EH
                    + (ks * 16 + brow) * 528 + (wn * 32 + bb * 16) * 2 + bcol;
                LDSM4T(bhh, addr);
                LDSM4T(bll, addr + (PJ_EL - PJ_EH));
                #pragma unroll
                for (int mt = 0; mt < 4; mt++) {
                    MMA16816(acc[mt][bb*2],   ah[mt], bhh[0], bhh[1]);
                    MMA16816(acc[mt][bb*2+1], ah[mt], bhh[2], bhh[3]);
                    MMA16816(acc[mt][bb*2],   ah[mt], bll[0], bll[1]);
                    MMA16816(acc[mt][bb*2+1], ah[mt], bll[2], bll[3]);
                    MMA16816(acc[mt][bb*2],   al[mt], bhh[0], bhh[1]);
                    MMA16816(acc[mt][bb*2+1], al[mt], bhh[2], bhh[3]);
                }
            }
        }
        __syncthreads();
    }

    const int grp = lane >> 2, qp = lane & 3;
    #pragma unroll
    for (int mt = 0; mt < 4; mt++) {
        #pragma unroll
        for (int nt = 0; nt < 4; nt++) {
            const int d0 = mt * 16 + grp;
            const int r  = wn * 32 + nt * 8 + qp * 2;
            const size_t i0 = (size_t)bh * DK_ * R_ + (size_t)d0 * R_ + r;
            const size_t i1 = i0 + 8 * R_;
            float v0 = acc[mt][nt][0], v1 = acc[mt][nt][1];
            float v2 = acc[mt][nt][2], v3 = acc[mt][nt][3];
            float h0 = __bfloat162float(__float2bfloat16(v0));
            float h1 = __bfloat162float(__float2bfloat16(v1));
            float h2 = __bfloat162float(__float2bfloat16(v2));
            float h3 = __bfloat162float(__float2bfloat16(v3));
            *(uint32_t*)(Oh + i0) = pack_bf2(v0, v1);
            *(uint32_t*)(Ol + i0) = pack_bf2(v0 - h0, v1 - h1);
            *(uint32_t*)(Oh + i1) = pack_bf2(v2, v3);
            *(uint32_t*)(Ol + i1) = pack_bf2(v2 - h2, v3 - h3);
        }
    }
}

// ============================================================================
// attention (HMMA): per block 64 s-rows x one (b,h).  Epilogue now writes
// split bf16 straight into g_ah/g_al (staging for the final Wo GEMM).
// ============================================================================
#define AT_QH   0
#define AT_QL   9216
#define AT_KPH  18432
#define AT_KPL  52224
#define AT_VPH  86016
#define AT_VPL  119808
#define AT_OUT  153600
#define AT_RED0 170496
#define AT_RED1 171008
#define AT_SMEM 171520

__global__ __launch_bounds__(256, 1) void attn_mma()
{
    extern __shared__ char sm[];
    const uint32_t sb = smem_u32(sm);
    const int bh = blockIdx.y, b = bh >> 4, h = bh & 15;
    const int s0 = blockIdx.x * 64;
    const int tid = threadIdx.x, wid = tid >> 5, lane = tid & 31;
    const int wm = wid & 3, wn = wid >> 2;

    #pragma unroll
    for (int i = 0; i < 36; i++) {
        const int c = tid + i * 256;
        uint32_t dst; const __nv_bfloat16* src;
        if (c < 1024) {
            const int sp = c >> 9, idx = c & 511, row = idx >> 3, ch = idx & 7;
            dst = sb + (sp ? AT_QL : AT_QH) + row * 144 + ch * 16;
            src = (sp ? g_ql : g_qh) + ((size_t)(b * S_ + s0 + row) * D_ + h * DK_ + ch * 8);
        } else if (c < 5120) {
            const int i2 = c - 1024, sp = i2 >> 11, idx = i2 & 2047;
            const int row = idx >> 5, ch = idx & 31;
            dst = sb + (sp ? AT_KPL : AT_KPH) + row * 528 + ch * 16;
            src = (sp ? g_kpl : g_kph) + ((size_t)bh * DK_ * R_ + row * R_ + ch * 8);
        } else {
            const int i2 = c - 5120, sp = i2 >> 11, idx = i2 & 2047;
            const int row = idx >> 5, ch = idx & 31;
            dst = sb + (sp ? AT_VPL : AT_VPH) + row * 528 + ch * 16;
            src = (sp ? g_vpl : g_vph) + ((size_t)bh * DK_ * R_ + row * R_ + ch * 8);
        }
        cp16(dst, src);
    }
    cp_commit(); cp_wait<0>();
    __syncthreads();

    float acc[16][4];
    #pragma unroll
    for (int j = 0; j < 16; j++)
        #pragma unroll
        for (int e = 0; e < 4; e++) acc[j][e] = 0.f;

    #pragma unroll
    for (int kd = 0; kd < 4; kd++) {
        uint32_t ah[4], al[4];
        const uint32_t qaddr = sb + AT_QH
            + (wm * 16 + (lane & 15)) * 144 + kd * 32 + (lane >> 4) * 16;
        LDSM4(ah, qaddr);
        LDSM4(al, qaddr + (AT_QL - AT_QH));
        #pragma unroll
        for (int bb = 0; bb < 8; bb++) {
            uint32_t bhh[4], bll[4];
            const uint32_t baddr = sb + AT_KPH
                + (kd * 16 + (lane & 15)) * 528 + (wn * 128 + bb * 16) * 2 + (lane >> 4) * 16;
            LDSM4T(bhh, baddr);
            LDSM4T(bll, baddr + (AT_KPL - AT_KPH));
            MMA16816(acc[bb*2],   ah, bhh[0], bhh[1]);
            MMA16816(acc[bb*2+1], ah, bhh[2], bhh[3]);
            MMA16816(acc[bb*2],   ah, bll[0], bll[1]);
            MMA16816(acc[bb*2+1], ah, bll[2], bll[3]);
            MMA16816(acc[bb*2],   al, bhh[0], bhh[1]);
            MMA16816(acc[bb*2+1], al, bhh[2], bhh[3]);
        }
    }

    float* red0 = (float*)(sm + AT_RED0);
    float* red1 = (float*)(sm + AT_RED1);
    const int row0 = wm * 16 + (lane >> 2);
    const int row1 = row0 + 8;

    float mx0 = -1e30f, mx1 = -1e30f;
    #pragma unroll
    for (int j = 0; j < 16; j++) {
        mx0 = fmaxf(mx0, fmaxf(acc[j][0], acc[j][1]));
        mx1 = fmaxf(mx1, fmaxf(acc[j][2], acc[j][3]));
    }
    mx0 = fmaxf(mx0, __shfl_xor_sync(0xffffffffu, mx0, 1));
    mx0 = fmaxf(mx0, __shfl_xor_sync(0xffffffffu, mx0, 2));
    mx1 = fmaxf(mx1, __shfl_xor_sync(0xffffffffu, mx1, 1));
    mx1 = fmaxf(mx1, __shfl_xor_sync(0xffffffffu, mx1, 2));
    if ((lane & 3) == 0) { red0[row0 * 2 + wn] = mx0; red0[row1 * 2 + wn] = mx1; }
    __syncthreads();
    const float m0 = fmaxf(red0[row0 * 2], red0[row0 * 2 + 1]);
    const float m1 = fmaxf(red0[row1 * 2], red0[row1 * 2 + 1]);

    float su0 = 0.f, su1 = 0.f;
    #pragma unroll
    for (int j = 0; j < 16; j++) {
        acc[j][0] = __expf((acc[j][0] - m0) * 0.125f);
        acc[j][1] = __expf((acc[j][1] - m0) * 0.125f);
        acc[j][2] = __expf((acc[j][2] - m1) * 0.125f);
        acc[j][3] = __expf((acc[j][3] - m1) * 0.125f);
        su0 += acc[j][0] + acc[j][1];
        su1 += acc[j][2] + acc[j][3];
    }
    su0 += __shfl_xor_sync(0xffffffffu, su0, 1);
    su0 += __shfl_xor_sync(0xffffffffu, su0, 2);
    su1 += __shfl_xor_sync(0xffffffffu, su1, 1);
    su1 += __shfl_xor_sync(0xffffffffu, su1, 2);
    if ((lane & 3) == 0) { red1[row0 * 2 + wn] = su0; red1[row1 * 2 + wn] = su1; }
    __syncthreads();
    const float inv0 = 1.f / (red1[row0 * 2] + red1[row0 * 2 + 1]);
    const float inv1 = 1.f / (red1[row1 * 2] + red1[row1 * 2 + 1]);

    uint32_t ph[16][2], pl[16][2];
    #pragma unroll
    for (int j = 0; j < 16; j++) {
        const float p0 = acc[j][0] * inv0, p1 = acc[j][1] * inv0;
        const float p2 = acc[j][2] * inv1, p3 = acc[j][3] * inv1;
        const float h0 = __bfloat162float(__float2bfloat16(p0));
        const float h1 = __bfloat162float(__float2bfloat16(p1));
        const float h2 = __bfloat162float(__float2bfloat16(p2));
        const float h3 = __bfloat162float(__float2bfloat16(p3));
        ph[j][0] = pack_bf2(p0, p1);       ph[j][1] = pack_bf2(p2, p3);
        pl[j][0] = pack_bf2(p0 - h0, p1 - h1);
        pl[j][1] = pack_bf2(p2 - h2, p3 - h3);
    }

    float acc2[8][4];
    #pragma unroll
    for (int nn = 0; nn < 8; nn++)
        #pragma unroll
        for (int e = 0; e < 4; e++) acc2[nn][e] = 0.f;

    #pragma unroll
    for (int jj = 0; jj < 8; jj++) {
        uint32_t a_h[4] = { ph[2*jj][0], ph[2*jj][1], ph[2*jj+1][0], ph[2*jj+1][1] };
        uint32_t a_l[4] = { pl[2*jj][0], pl[2*jj][1], pl[2*jj+1][0], pl[2*jj+1][1] };
        #pragma unroll
        for (int nb = 0; nb < 4; nb++) {
            uint32_t bhh[4], bll[4];
            const uint32_t baddr = sb + AT_VPH
                + (nb * 16 + (lane & 15)) * 528 + (wn * 128 + jj * 16) * 2 + (lane >> 4) * 16;
            LDSM4(bhh, baddr);
            LDSM4(bll, baddr + (AT_VPL - AT_VPH));
            MMA16816(acc2[nb*2],   a_h, bhh[0], bhh[2]);
            MMA16816(acc2[nb*2+1], a_h, bhh[1], bhh[3]);
            MMA16816(acc2[nb*2],   a_h, bll[0], bll[2]);
            MMA16816(acc2[nb*2+1], a_h, bll[1], bll[3]);
            MMA16816(acc2[nb*2],   a_l, bhh[0], bhh[2]);
            MMA16816(acc2[nb*2+1], a_l, bhh[1], bhh[3]);
        }
    }

    float* outb = (float*)(sm + AT_OUT);
    const int qp = lane & 3;
    __syncthreads();
    if (wn == 1) {
        #pragma unroll
        for (int nn = 0; nn < 8; nn++) {
            const int c = nn * 8 + qp * 2;
            outb[row0 * 66 + c] = acc2[nn][0]; outb[row0 * 66 + c + 1] = acc2[nn][1];
            outb[row1 * 66 + c] = acc2[nn][2]; outb[row1 * 66 + c + 1] = acc2[nn][3];
        }
    }
    __syncthreads();
    if (wn == 0) {
        #pragma unroll
        for (int nn = 0; nn < 8; nn++) {
            const int c = nn * 8 + qp * 2;
            const float v0 = acc2[nn][0] + outb[row0 * 66 + c];
            const float v1 = acc2[nn][1] + outb[row0 * 66 + c + 1];
            const float v2 = acc2[nn][2] + outb[row1 * 66 + c];
            const float v3 = acc2[nn][3] + outb[row1 * 66 + c + 1];
            const float h0 = __bfloat162float(__float2bfloat16(v0));
            const float h1 = __bfloat162float(__float2bfloat16(v1));
            const float h2 = __bfloat162float(__float2bfloat16(v2));
            const float h3 = __bfloat162float(__float2bfloat16(v3));
            const size_t o0 = (size_t)(b * S_ + s0 + row0) * D_ + h * DK_ + c;
            const size_t o1 = (size_t)(b * S_ + s0 + row1) * D_ + h * DK_ + c;
            *(uint32_t*)(g_ah + o0) = pack_bf2(v0, v1);
            *(uint32_t*)(g_al + o0) = pack_bf2(v0 - h0, v1 - h1);
            *(uint32_t*)(g_ah + o1) = pack_bf2(v2, v3);
            *(uint32_t*)(g_al + o1) = pack_bf2(v2 - h2, v3 - h3);
        }
    }
}

// ============================================================================
extern "C" void kernel_launch(void* const* d_in, const int* in_sizes, int n_in,
                              void* d_out, int out_size)
{
    const float* query = (const float*)d_in[0];
    const float* key   = (const float*)d_in[1];
    const float* value = (const float*)d_in[2];
    const float* Wq = (const float*)d_in[3];
    const float* bq = (const float*)d_in[4];
    const float* Wk = (const float*)d_in[5];
    const float* bk = (const float*)d_in[6];
    const float* Wv = (const float*)d_in[7];
    const float* bv = (const float*)d_in[8];
    const float* Wo = (const float*)d_in[9];
    const float* bo = (const float*)d_in[10];
    const float* E  = (const float*)d_in[11];
    const float* F  = (const float*)d_in[12];
    float* out = (float*)d_out;

    cudaFuncSetAttribute(mm_gemm,  cudaFuncAttributeMaxDynamicSharedMemorySize, GSMEM_B);
    cudaFuncSetAttribute(proj_mma, cudaFuncAttributeMaxDynamicSharedMemorySize, PJ_SMEM);
    cudaFuncSetAttribute(attn_mma, cudaFuncAttributeMaxDynamicSharedMemorySize, AT_SMEM);

    const int nA4 = M_ * D_ / 4;
    const int nW4 = D_ * D_ / 4;
    const int nE4 = H_ * S_ * R_ / 4;
    const dim3 gg(D_ / 128, M_ / 128);

    conv_kernel<<<nA4 / 256, 256>>>(query, 0, nA4);
    conv_kernel<<<nW4 / 256, 256>>>(Wq,    1, nW4);
    mm_gemm<<<gg, 512, GSMEM_B>>>(bq, nullptr, 0);

    conv_kernel<<<nA4 / 256, 256>>>(key, 0, nA4);
    conv_kernel<<<nW4 / 256, 256>>>(Wk,  1, nW4);
    mm_gemm<<<gg, 512, GSMEM_B>>>(bk, nullptr, 1);

    conv_kernel<<<nA4 / 256, 256>>>(value, 0, nA4);
    conv_kernel<<<nW4 / 256, 256>>>(Wv,    1, nW4);
    mm_gemm<<<gg, 512, GSMEM_B>>>(bv, nullptr, 2);

    conv_kernel<<<nE4 / 256, 256>>>(E, 2, nE4);
    conv_kernel<<<nE4 / 256, 256>>>(F, 3, nE4);

    proj_mma<<<128, 256, PJ_SMEM>>>();
    attn_mma<<<dim3(64, 64), 256, AT_SMEM>>>();

    conv_kernel<<<nW4 / 256, 256>>>(Wo, 1, nW4);
    mm_gemm<<<gg, 512, GSMEM_B>>>(bo, out, 3);
}